// round 1
// baseline (speedup 1.0000x reference)
#include <cuda_runtime.h>
#include <cuda_bf16.h>
#include <cstdint>

#define N_NODES 50000
#define N_EDGES 800000
#define EDGE_DIM 64
#define NODE_DIM 256
#define HIDDEN   512
#define OUT_DIM  256
#define K1DIM    (EDGE_DIM + NODE_DIM)   // 320

// ---------------- device scratch (no allocations allowed) ----------------
__device__ int   g_cnt[N_NODES];
__device__ int   g_off[N_NODES + 1];
__device__ int   g_cur[N_NODES];
__device__ int   g_elist[N_EDGES];
__device__ float g_agg[(size_t)N_NODES * EDGE_DIM];
__device__ float g_h[(size_t)N_NODES * HIDDEN];
__device__ int   g_is64;

// ---------------- dtype detection (jax x32 may deliver int32) ----------------
__global__ void detect_k(const void* __restrict__ eidx) {
    __shared__ int bad;
    if (threadIdx.x == 0) bad = 0;
    __syncthreads();
    // Reading the first 1024 int64 slots is in-bounds even if the buffer is int32
    // (int32 buffer = 6.4MB = 800000 int64 slots).
    long long v = ((const long long*)eidx)[threadIdx.x];
    if (v < 0 || v >= (long long)N_NODES) bad = 1;
    __syncthreads();
    if (threadIdx.x == 0) g_is64 = bad ? 0 : 1;
}

__device__ __forceinline__ int load_tgt(const void* __restrict__ eidx, int e) {
    if (g_is64) return (int)((const long long*)eidx)[N_EDGES + e];
    return ((const int*)eidx)[N_EDGES + e];
}

// ---------------- CSR build ----------------
__global__ void zero_k() {
    int i = blockIdx.x * blockDim.x + threadIdx.x;
    if (i < N_NODES) g_cnt[i] = 0;
}

__global__ void count_k(const void* __restrict__ eidx) {
    int e = blockIdx.x * blockDim.x + threadIdx.x;
    if (e < N_EDGES) atomicAdd(&g_cnt[load_tgt(eidx, e)], 1);
}

__global__ void scan_k() {
    __shared__ int sh[1024];
    int tid = threadIdx.x;
    const int CH = (N_NODES + 1023) / 1024;
    int s0 = tid * CH;
    int s1 = min(s0 + CH, N_NODES);
    int s = 0;
    for (int i = s0; i < s1; i++) s += g_cnt[i];
    sh[tid] = s;
    __syncthreads();
    for (int off = 1; off < 1024; off <<= 1) {
        int v = (tid >= off) ? sh[tid - off] : 0;
        __syncthreads();
        sh[tid] += v;
        __syncthreads();
    }
    int run = sh[tid] - s;   // exclusive prefix for this chunk
    for (int i = s0; i < s1; i++) {
        g_off[i] = run;
        g_cur[i] = run;
        run += g_cnt[i];
    }
    if (tid == 1023) g_off[N_NODES] = sh[1023];
}

__global__ void fill_k(const void* __restrict__ eidx) {
    int e = blockIdx.x * blockDim.x + threadIdx.x;
    if (e < N_EDGES) {
        int t = load_tgt(eidx, e);
        int p = atomicAdd(&g_cur[t], 1);
        g_elist[p] = e;
    }
}

// ---------------- mean aggregation: one warp per node ----------------
__global__ void agg_k(const float* __restrict__ ef) {
    int n = blockIdx.x * 8 + (threadIdx.x >> 5);      // grid = N_NODES/8 exactly
    int lane = threadIdx.x & 31;
    int base = g_off[n];
    int deg  = g_off[n + 1] - base;
    float ax = 0.f, ay = 0.f;
    const float2* ef2 = (const float2*)ef;
    int i = 0;
    for (; i + 2 <= deg; i += 2) {
        int e0 = g_elist[base + i];
        int e1 = g_elist[base + i + 1];
        float2 v0 = ef2[(size_t)e0 * 32 + lane];
        float2 v1 = ef2[(size_t)e1 * 32 + lane];
        ax += v0.x + v1.x;
        ay += v0.y + v1.y;
    }
    if (i < deg) {
        int e0 = g_elist[base + i];
        float2 v0 = ef2[(size_t)e0 * 32 + lane];
        ax += v0.x;
        ay += v0.y;
    }
    float inv = 1.f / fmaxf((float)deg, 1.f);
    float2 r;
    r.x = ax * inv;
    r.y = ay * inv;
    ((float2*)g_agg)[(size_t)n * 32 + lane] = r;
}

// ---------------- tf32 GEMM (mma.sync m16n8k8) ----------------
__device__ __forceinline__ uint32_t f2tf(float x) {
    uint32_t u;
    asm("cvt.rna.tf32.f32 %0, %1;" : "=r"(u) : "f"(x));
    return u;
}

__device__ __forceinline__ void mma_tf32(float& c0, float& c1, float& c2, float& c3,
                                         uint32_t a0, uint32_t a1, uint32_t a2, uint32_t a3,
                                         uint32_t b0, uint32_t b1) {
    asm volatile(
        "mma.sync.aligned.m16n8k8.row.col.f32.tf32.tf32.f32 "
        "{%0,%1,%2,%3}, {%4,%5,%6,%7}, {%8,%9}, {%0,%1,%2,%3};\n"
        : "+f"(c0), "+f"(c1), "+f"(c2), "+f"(c3)
        : "r"(a0), "r"(a1), "r"(a2), "r"(a3), "r"(b0), "r"(b1));
}

// Block tile 128x128, BK=32, 256 threads, warp tile 32x64 (2 m-frags x 8 n-frags)
template <bool CONCAT, bool RELU>
__device__ __forceinline__ void gemm_body(const float* __restrict__ A0,
                                          const float* __restrict__ A1,
                                          const float* __restrict__ B,
                                          const float* __restrict__ bias,
                                          float* __restrict__ C,
                                          int M, int N, int K) {
    __shared__ uint32_t As[32][132];   // [k][m], padded
    __shared__ uint32_t Bs[32][132];   // [k][n], padded

    const int bm = blockIdx.y * 128;
    const int bn = blockIdx.x * 128;
    const int tid = threadIdx.x;
    const int lane = tid & 31;
    const int wid = tid >> 5;
    const int wm = (wid & 3) * 32;
    const int wn = (wid >> 2) * 64;
    const int g = lane >> 2;     // groupID
    const int tg = lane & 3;     // thread-in-group

    float acc[2][8][4];
#pragma unroll
    for (int mi = 0; mi < 2; mi++)
#pragma unroll
        for (int ni = 0; ni < 8; ni++)
#pragma unroll
            for (int q = 0; q < 4; q++) acc[mi][ni][q] = 0.f;

    for (int k0 = 0; k0 < K; k0 += 32) {
        // ---- load A tile 128x32 ----
#pragma unroll
        for (int p = 0; p < 4; p++) {
            int row = p * 32 + (tid >> 3);
            int col = (tid & 7) * 4;
            int gr = bm + row;
            float4 v = make_float4(0.f, 0.f, 0.f, 0.f);
            if (gr < M) {
                const float* src;
                if (CONCAT) {
                    int gk = k0 + col;
                    if (gk < EDGE_DIM) src = A0 + (size_t)gr * EDGE_DIM + gk;
                    else               src = A1 + (size_t)gr * NODE_DIM + (gk - EDGE_DIM);
                } else {
                    src = A0 + (size_t)gr * K + (k0 + col);
                }
                v = *(const float4*)src;
            }
            As[col + 0][row] = f2tf(v.x);
            As[col + 1][row] = f2tf(v.y);
            As[col + 2][row] = f2tf(v.z);
            As[col + 3][row] = f2tf(v.w);
        }
        // ---- load B tile 32x128 ----
#pragma unroll
        for (int p = 0; p < 4; p++) {
            int row = p * 8 + (tid >> 5);
            int col = (tid & 31) * 4;
            float4 v = *(const float4*)(B + (size_t)(k0 + row) * N + bn + col);
            Bs[row][col + 0] = f2tf(v.x);
            Bs[row][col + 1] = f2tf(v.y);
            Bs[row][col + 2] = f2tf(v.z);
            Bs[row][col + 3] = f2tf(v.w);
        }
        __syncthreads();

#pragma unroll
        for (int kk = 0; kk < 32; kk += 8) {
            uint32_t a[2][4], b[8][2];
#pragma unroll
            for (int mi = 0; mi < 2; mi++) {
                int m = wm + mi * 16 + g;
                a[mi][0] = As[kk + tg][m];
                a[mi][1] = As[kk + tg][m + 8];
                a[mi][2] = As[kk + tg + 4][m];
                a[mi][3] = As[kk + tg + 4][m + 8];
            }
#pragma unroll
            for (int ni = 0; ni < 8; ni++) {
                int n = wn + ni * 8 + g;
                b[ni][0] = Bs[kk + tg][n];
                b[ni][1] = Bs[kk + tg + 4][n];
            }
#pragma unroll
            for (int mi = 0; mi < 2; mi++)
#pragma unroll
                for (int ni = 0; ni < 8; ni++)
                    mma_tf32(acc[mi][ni][0], acc[mi][ni][1], acc[mi][ni][2], acc[mi][ni][3],
                             a[mi][0], a[mi][1], a[mi][2], a[mi][3],
                             b[ni][0], b[ni][1]);
        }
        __syncthreads();
    }

    // ---- epilogue: bias (+relu) ----
#pragma unroll
    for (int mi = 0; mi < 2; mi++) {
        int r0 = bm + wm + mi * 16 + g;
#pragma unroll
        for (int ni = 0; ni < 8; ni++) {
            int c0 = bn + wn + ni * 8 + tg * 2;
            float b0 = bias[c0];
            float b1 = bias[c0 + 1];
            float v0 = acc[mi][ni][0] + b0;
            float v1 = acc[mi][ni][1] + b1;
            float v2 = acc[mi][ni][2] + b0;
            float v3 = acc[mi][ni][3] + b1;
            if (RELU) {
                v0 = fmaxf(v0, 0.f); v1 = fmaxf(v1, 0.f);
                v2 = fmaxf(v2, 0.f); v3 = fmaxf(v3, 0.f);
            }
            if (r0 < M) {
                C[(size_t)r0 * N + c0] = v0;
                C[(size_t)r0 * N + c0 + 1] = v1;
            }
            if (r0 + 8 < M) {
                C[(size_t)(r0 + 8) * N + c0] = v2;
                C[(size_t)(r0 + 8) * N + c0 + 1] = v3;
            }
        }
    }
}

__global__ void __launch_bounds__(256) gemm1_k(const float* __restrict__ node,
                                               const float* __restrict__ W1,
                                               const float* __restrict__ b1) {
    gemm_body<true, true>(g_agg, node, W1, b1, g_h, N_NODES, HIDDEN, K1DIM);
}

__global__ void __launch_bounds__(256) gemm2_k(const float* __restrict__ W2,
                                               const float* __restrict__ b2,
                                               float* __restrict__ out) {
    gemm_body<false, false>(g_h, nullptr, W2, b2, out, N_NODES, OUT_DIM, HIDDEN);
}

// ---------------- launch ----------------
extern "C" void kernel_launch(void* const* d_in, const int* in_sizes, int n_in,
                              void* d_out, int out_size) {
    const float* node = (const float*)d_in[0];
    const void*  eidx = d_in[1];                 // int64 or int32 (detected on device)
    const float* ef   = (const float*)d_in[2];
    const float* W1   = (const float*)d_in[3];
    const float* b1   = (const float*)d_in[4];
    const float* W2   = (const float*)d_in[5];
    const float* b2   = (const float*)d_in[6];
    float* out = (float*)d_out;

    detect_k<<<1, 1024>>>(eidx);
    zero_k<<<(N_NODES + 255) / 256, 256>>>();
    count_k<<<(N_EDGES + 255) / 256, 256>>>(eidx);
    scan_k<<<1, 1024>>>();
    fill_k<<<(N_EDGES + 255) / 256, 256>>>(eidx);
    agg_k<<<N_NODES / 8, 256>>>(ef);
    gemm1_k<<<dim3(HIDDEN / 128, (N_NODES + 127) / 128), 256>>>(node, W1, b1);
    gemm2_k<<<dim3(OUT_DIM / 128, (N_NODES + 127) / 128), 256>>>(W2, b2, out);
}

// round 2
// speedup vs baseline: 1.7464x; 1.7464x over previous
#include <cuda_runtime.h>
#include <cuda_bf16.h>
#include <cstdint>

#define N_NODES 50000
#define N_EDGES 800000
#define EDGE_DIM 64
#define NODE_DIM 256
#define HIDDEN   512
#define OUT_DIM  256
#define K1DIM    (EDGE_DIM + NODE_DIM)   // 320
#define M_PAD    50048                   // 391 * 128
#define NBLK     49                      // ceil(N_NODES/1024)

// ---------------- device scratch ----------------
__device__ int   g_cnt[N_NODES];
__device__ int   g_off[N_NODES + 1];
__device__ int   g_cur[N_NODES];
__device__ int   g_bsum[NBLK];
__device__ int   g_elist[N_EDGES];
__device__ float g_A1[(size_t)M_PAD * K1DIM];       // tf32-rounded [agg | node]
__device__ float g_h[(size_t)M_PAD * HIDDEN];       // tf32-rounded hidden
__device__ float g_W1t[K1DIM * HIDDEN];
__device__ float g_W2t[HIDDEN * OUT_DIM];
__device__ int   g_is64;

// ---------------- helpers ----------------
__device__ __forceinline__ uint32_t f2tf(float x) {
    uint32_t u;
    asm("cvt.rna.tf32.f32 %0, %1;" : "=r"(u) : "f"(x));
    return u;
}
__device__ __forceinline__ float f2tf_f(float x) { return __uint_as_float(f2tf(x)); }

__device__ __forceinline__ uint32_t sptr(const void* p) {
    return (uint32_t)__cvta_generic_to_shared(p);
}
__device__ __forceinline__ void cpa16(uint32_t d, const void* s) {
    asm volatile("cp.async.cg.shared.global [%0], [%1], 16;" :: "r"(d), "l"(s));
}
__device__ __forceinline__ void cp_commit() { asm volatile("cp.async.commit_group;"); }
template <int W> __device__ __forceinline__ void cp_wait() {
    asm volatile("cp.async.wait_group %0;" :: "n"(W));
}

// ---------------- dtype detection ----------------
__global__ void detect_k(const void* __restrict__ eidx) {
    __shared__ int bad;
    if (threadIdx.x == 0) bad = 0;
    __syncthreads();
    long long v = ((const long long*)eidx)[threadIdx.x];
    if (v < 0 || v >= (long long)N_NODES) bad = 1;
    __syncthreads();
    if (threadIdx.x == 0) g_is64 = bad ? 0 : 1;
}

__device__ __forceinline__ int load_tgt(const void* __restrict__ eidx, int e) {
    if (g_is64) return (int)((const long long*)eidx)[N_EDGES + e];
    return ((const int*)eidx)[N_EDGES + e];
}

// ---------------- CSR build ----------------
__global__ void zero_k() {
    int i = blockIdx.x * blockDim.x + threadIdx.x;
    if (i < N_NODES) g_cnt[i] = 0;
}

__global__ void count_k(const void* __restrict__ eidx) {
    int e = blockIdx.x * blockDim.x + threadIdx.x;
    if (e < N_EDGES) atomicAdd(&g_cnt[load_tgt(eidx, e)], 1);
}

__global__ void blocksum_k() {
    int i = blockIdx.x * 1024 + threadIdx.x;
    int v = (i < N_NODES) ? g_cnt[i] : 0;
    int lane = threadIdx.x & 31, w = threadIdx.x >> 5;
    __shared__ int ws[32];
#pragma unroll
    for (int o = 16; o; o >>= 1) v += __shfl_down_sync(~0u, v, o);
    if (lane == 0) ws[w] = v;
    __syncthreads();
    if (w == 0) {
        v = ws[lane];
#pragma unroll
        for (int o = 16; o; o >>= 1) v += __shfl_down_sync(~0u, v, o);
        if (lane == 0) g_bsum[blockIdx.x] = v;
    }
}

__global__ void scanb_k() {   // 1 block, 64 threads
    __shared__ int s[64];
    int t = threadIdx.x;
    int orig = (t < NBLK) ? g_bsum[t] : 0;
    s[t] = orig;
    __syncthreads();
#pragma unroll
    for (int o = 1; o < 64; o <<= 1) {
        int v = (t >= o) ? s[t - o] : 0;
        __syncthreads();
        s[t] += v;
        __syncthreads();
    }
    if (t < NBLK) g_bsum[t] = s[t] - orig;   // exclusive block prefix
    if (t == 63) g_off[N_NODES] = s[63];
}

__global__ void scatter_k() {
    int tid = threadIdx.x;
    int i = blockIdx.x * 1024 + tid;
    int c = (i < N_NODES) ? g_cnt[i] : 0;
    int lane = tid & 31, w = tid >> 5;
    int inc = c;
#pragma unroll
    for (int o = 1; o < 32; o <<= 1) {
        int t = __shfl_up_sync(~0u, inc, o);
        if (lane >= o) inc += t;
    }
    __shared__ int wsum[32];
    if (lane == 31) wsum[w] = inc;
    __syncthreads();
    if (w == 0) {
        int x = wsum[lane];
#pragma unroll
        for (int o = 1; o < 32; o <<= 1) {
            int t = __shfl_up_sync(~0u, x, o);
            if (lane >= o) x += t;
        }
        wsum[lane] = x;
    }
    __syncthreads();
    int base = (w > 0) ? wsum[w - 1] : 0;
    int excl = base + inc - c;
    if (i < N_NODES) {
        int off = g_bsum[blockIdx.x] + excl;
        g_off[i] = off;
        g_cur[i] = off;
    }
}

__global__ void fill_k(const void* __restrict__ eidx) {
    int e = blockIdx.x * blockDim.x + threadIdx.x;
    if (e < N_EDGES) {
        int t = load_tgt(eidx, e);
        int p = atomicAdd(&g_cur[t], 1);
        g_elist[p] = e;
    }
}

// ---------------- mean aggregation: one warp per node, writes tf32 into g_A1 ----------------
__global__ void agg_k(const float* __restrict__ ef) {
    int n = blockIdx.x * 8 + (threadIdx.x >> 5);      // grid = N_NODES/8 exactly
    int lane = threadIdx.x & 31;
    int base = g_off[n];
    int deg  = g_off[n + 1] - base;
    float ax = 0.f, ay = 0.f;
    const float2* ef2 = (const float2*)ef;
    int i = 0;
    for (; i + 2 <= deg; i += 2) {
        int e0 = g_elist[base + i];
        int e1 = g_elist[base + i + 1];
        float2 v0 = ef2[(size_t)e0 * 32 + lane];
        float2 v1 = ef2[(size_t)e1 * 32 + lane];
        ax += v0.x + v1.x;
        ay += v0.y + v1.y;
    }
    if (i < deg) {
        int e0 = g_elist[base + i];
        float2 v0 = ef2[(size_t)e0 * 32 + lane];
        ax += v0.x;
        ay += v0.y;
    }
    float inv = 1.f / fmaxf((float)deg, 1.f);
    float2 r;
    r.x = f2tf_f(ax * inv);
    r.y = f2tf_f(ay * inv);
    *(float2*)&g_A1[(size_t)n * K1DIM + lane * 2] = r;
}

// ---------------- node feature copy + tf32 round into g_A1 cols [64,320) ----------------
__global__ void node_cvt_k(const float* __restrict__ node) {
    int idx = blockIdx.x * blockDim.x + threadIdx.x;   // over N_NODES*64 float4s
    if (idx < N_NODES * 64) {
        int n = idx >> 6, q = idx & 63;
        float4 v = ((const float4*)node)[idx];
        v.x = f2tf_f(v.x); v.y = f2tf_f(v.y); v.z = f2tf_f(v.z); v.w = f2tf_f(v.w);
        *(float4*)&g_A1[(size_t)n * K1DIM + EDGE_DIM + q * 4] = v;
    }
}

// ---------------- weight conversion ----------------
#define W1_F4 (K1DIM * HIDDEN / 4)     // 40960
#define W2_F4 (HIDDEN * OUT_DIM / 4)   // 32768
__global__ void w_cvt_k(const float* __restrict__ W1, const float* __restrict__ W2) {
    int idx = blockIdx.x * blockDim.x + threadIdx.x;
    if (idx < W1_F4 + W2_F4) {
        const float4* src = (idx < W1_F4) ? &((const float4*)W1)[idx]
                                          : &((const float4*)W2)[idx - W1_F4];
        float4 v = *src;
        v.x = f2tf_f(v.x); v.y = f2tf_f(v.y); v.z = f2tf_f(v.z); v.w = f2tf_f(v.w);
        if (idx < W1_F4) ((float4*)g_W1t)[idx] = v;
        else             ((float4*)g_W2t)[idx - W1_F4] = v;
    }
}

// ---------------- tf32 GEMM: 128x128 block, BK=16, 2-stage cp.async ----------------
__device__ __forceinline__ void mma_tf32(float& c0, float& c1, float& c2, float& c3,
                                         uint32_t a0, uint32_t a1, uint32_t a2, uint32_t a3,
                                         uint32_t b0, uint32_t b1) {
    asm volatile(
        "mma.sync.aligned.m16n8k8.row.col.f32.tf32.tf32.f32 "
        "{%0,%1,%2,%3}, {%4,%5,%6,%7}, {%8,%9}, {%0,%1,%2,%3};\n"
        : "+f"(c0), "+f"(c1), "+f"(c2), "+f"(c3)
        : "r"(a0), "r"(a1), "r"(a2), "r"(a3), "r"(b0), "r"(b1));
}

template <int K, int N, bool RELU, bool STORE_TF, bool GUARD>
__global__ void __launch_bounds__(256) gemm_k(const float* __restrict__ A,
                                              const float* __restrict__ B,
                                              const float* __restrict__ bias,
                                              float* __restrict__ C) {
    __shared__ float As[2][128][20];    // [m][k], pad 4 -> bank (20g+tg)%32 distinct
    __shared__ float Bs[2][16][136];    // [k][n], pad 8 -> bank (8tg+g)%32 distinct

    const int bm = blockIdx.y * 128;
    const int bn = blockIdx.x * 128;
    const int tid = threadIdx.x, lane = tid & 31, wid = tid >> 5;
    const int wm = (wid & 3) * 32, wn = (wid >> 2) * 64;
    const int g = lane >> 2, tg = lane & 3;

    const int aRow0 = tid >> 2, aK = (tid & 3) * 4;
    const int aRow1 = aRow0 + 64;
    const int bRow  = tid >> 5, bCol = lane * 4;

    const float* aSrc0 = A + (size_t)(bm + aRow0) * K + aK;
    const float* aSrc1 = A + (size_t)(bm + aRow1) * K + aK;
    const float* bSrc0 = B + (size_t)bRow * N + bn + bCol;
    const float* bSrc1 = B + (size_t)(bRow + 8) * N + bn + bCol;

    float acc[2][8][4];
#pragma unroll
    for (int mi = 0; mi < 2; mi++)
#pragma unroll
        for (int ni = 0; ni < 8; ni++)
#pragma unroll
            for (int q = 0; q < 4; q++) acc[mi][ni][q] = 0.f;

#define LOAD_TILE(S, K0)                                                     \
    do {                                                                     \
        cpa16(sptr(&As[S][aRow0][aK]), aSrc0 + (K0));                        \
        cpa16(sptr(&As[S][aRow1][aK]), aSrc1 + (K0));                        \
        cpa16(sptr(&Bs[S][bRow][bCol]), bSrc0 + (size_t)(K0) * N);           \
        cpa16(sptr(&Bs[S][bRow + 8][bCol]), bSrc1 + (size_t)(K0) * N);       \
        cp_commit();                                                         \
    } while (0)

    const int NK = K / 16;
    LOAD_TILE(0, 0);
    int s = 0;
    for (int it = 0; it < NK; it++) {
        if (it + 1 < NK) {
            LOAD_TILE(s ^ 1, (it + 1) * 16);
            cp_wait<1>();
        } else {
            cp_wait<0>();
        }
        __syncthreads();
#pragma unroll
        for (int kk = 0; kk < 16; kk += 8) {
            uint32_t a[2][4], b[8][2];
#pragma unroll
            for (int mi = 0; mi < 2; mi++) {
                int m = wm + mi * 16 + g;
                a[mi][0] = __float_as_uint(As[s][m][kk + tg]);
                a[mi][1] = __float_as_uint(As[s][m + 8][kk + tg]);
                a[mi][2] = __float_as_uint(As[s][m][kk + tg + 4]);
                a[mi][3] = __float_as_uint(As[s][m + 8][kk + tg + 4]);
            }
#pragma unroll
            for (int ni = 0; ni < 8; ni++) {
                int n = wn + ni * 8 + g;
                b[ni][0] = __float_as_uint(Bs[s][kk + tg][n]);
                b[ni][1] = __float_as_uint(Bs[s][kk + tg + 4][n]);
            }
#pragma unroll
            for (int mi = 0; mi < 2; mi++)
#pragma unroll
                for (int ni = 0; ni < 8; ni++)
                    mma_tf32(acc[mi][ni][0], acc[mi][ni][1], acc[mi][ni][2], acc[mi][ni][3],
                             a[mi][0], a[mi][1], a[mi][2], a[mi][3],
                             b[ni][0], b[ni][1]);
        }
        __syncthreads();
        s ^= 1;
    }
#undef LOAD_TILE

    // epilogue: bias (+relu) (+tf32 round) (+row guard)
#pragma unroll
    for (int mi = 0; mi < 2; mi++) {
        int r0 = bm + wm + mi * 16 + g;
#pragma unroll
        for (int ni = 0; ni < 8; ni++) {
            int c0 = bn + wn + ni * 8 + tg * 2;
            float b0 = bias[c0];
            float b1 = bias[c0 + 1];
            float v0 = acc[mi][ni][0] + b0;
            float v1 = acc[mi][ni][1] + b1;
            float v2 = acc[mi][ni][2] + b0;
            float v3 = acc[mi][ni][3] + b1;
            if (RELU) {
                v0 = fmaxf(v0, 0.f); v1 = fmaxf(v1, 0.f);
                v2 = fmaxf(v2, 0.f); v3 = fmaxf(v3, 0.f);
            }
            if (STORE_TF) {
                v0 = f2tf_f(v0); v1 = f2tf_f(v1);
                v2 = f2tf_f(v2); v3 = f2tf_f(v3);
            }
            if (!GUARD || r0 < N_NODES) {
                C[(size_t)r0 * N + c0] = v0;
                C[(size_t)r0 * N + c0 + 1] = v1;
            }
            if (!GUARD || r0 + 8 < N_NODES) {
                C[(size_t)(r0 + 8) * N + c0] = v2;
                C[(size_t)(r0 + 8) * N + c0 + 1] = v3;
            }
        }
    }
}

// ---------------- launch ----------------
extern "C" void kernel_launch(void* const* d_in, const int* in_sizes, int n_in,
                              void* d_out, int out_size) {
    const float* node = (const float*)d_in[0];
    const void*  eidx = d_in[1];
    const float* ef   = (const float*)d_in[2];
    const float* W1   = (const float*)d_in[3];
    const float* b1   = (const float*)d_in[4];
    const float* W2   = (const float*)d_in[5];
    const float* b2   = (const float*)d_in[6];
    float* out = (float*)d_out;

    detect_k<<<1, 1024>>>(eidx);
    zero_k<<<(N_NODES + 255) / 256, 256>>>();
    count_k<<<(N_EDGES + 255) / 256, 256>>>(eidx);
    blocksum_k<<<NBLK, 1024>>>();
    scanb_k<<<1, 64>>>();
    scatter_k<<<NBLK, 1024>>>();
    fill_k<<<(N_EDGES + 255) / 256, 256>>>(eidx);
    agg_k<<<N_NODES / 8, 256>>>(ef);
    node_cvt_k<<<(N_NODES * 64 + 255) / 256, 256>>>(node);
    w_cvt_k<<<(W1_F4 + W2_F4 + 255) / 256, 256>>>(W1, W2);
    // h = relu([agg|node] @ W1 + b1), tf32-rounded, rows padded to M_PAD
    float* g_h_ptr;      cudaGetSymbolAddress((void**)&g_h_ptr, g_h);
    float* g_A1_ptr;     cudaGetSymbolAddress((void**)&g_A1_ptr, g_A1);
    float* g_W1t_ptr;    cudaGetSymbolAddress((void**)&g_W1t_ptr, g_W1t);
    float* g_W2t_ptr;    cudaGetSymbolAddress((void**)&g_W2t_ptr, g_W2t);
    gemm_k<K1DIM, HIDDEN, true, true, false>
        <<<dim3(HIDDEN / 128, M_PAD / 128), 256>>>(g_A1_ptr, g_W1t_ptr, b1, g_h_ptr);
    gemm_k<HIDDEN, OUT_DIM, false, false, true>
        <<<dim3(OUT_DIM / 128, M_PAD / 128), 256>>>(g_h_ptr, g_W2t_ptr, b2, out);
}

// round 4
// speedup vs baseline: 1.9206x; 1.0998x over previous
#include <cuda_runtime.h>
#include <cuda_bf16.h>
#include <cstdint>

#define N_NODES 50000
#define N_EDGES 800000
#define EDGE_DIM 64
#define NODE_DIM 256
#define HIDDEN   512
#define OUT_DIM  256
#define K1DIM    (EDGE_DIM + NODE_DIM)   // 320
#define M_PAD    50048                   // 391 * 128
#define NBLK     49

// ---------------- device scratch ----------------
__device__ int   g_cnt[N_NODES];
__device__ int   g_off[N_NODES + 1];
__device__ int   g_cur[N_NODES];
__device__ int   g_bsum[NBLK];
__device__ int   g_elist[N_EDGES];
__device__ float g_A1[(size_t)M_PAD * K1DIM];       // tf32-rounded [agg | node]
__device__ float g_h[(size_t)M_PAD * HIDDEN];       // tf32-rounded hidden
__device__ float g_W1t[HIDDEN * K1DIM];             // W1^T [N][K], tf32-rounded
__device__ float g_W2t[OUT_DIM * HIDDEN];           // W2^T [N][K], tf32-rounded
__device__ int   g_is64;

// ---------------- helpers ----------------
__device__ __forceinline__ uint32_t f2tf(float x) {
    uint32_t u;
    asm("cvt.rna.tf32.f32 %0, %1;" : "=r"(u) : "f"(x));
    return u;
}
__device__ __forceinline__ float f2tf_f(float x) { return __uint_as_float(f2tf(x)); }

__device__ __forceinline__ uint32_t sptr(const void* p) {
    return (uint32_t)__cvta_generic_to_shared(p);
}
__device__ __forceinline__ void cpa16(uint32_t d, const void* s) {
    asm volatile("cp.async.cg.shared.global [%0], [%1], 16;" :: "r"(d), "l"(s));
}
__device__ __forceinline__ void cp_commit() { asm volatile("cp.async.commit_group;"); }
template <int W> __device__ __forceinline__ void cp_wait() {
    asm volatile("cp.async.wait_group %0;" :: "n"(W));
}
__device__ __forceinline__ void ldsm4(uint32_t& r0, uint32_t& r1, uint32_t& r2,
                                      uint32_t& r3, uint32_t addr) {
    asm volatile("ldmatrix.sync.aligned.m8n8.x4.shared.b16 {%0,%1,%2,%3}, [%4];"
                 : "=r"(r0), "=r"(r1), "=r"(r2), "=r"(r3) : "r"(addr));
}

// ---------------- dtype detection ----------------
__global__ void detect_k(const void* __restrict__ eidx) {
    __shared__ int bad;
    if (threadIdx.x == 0) bad = 0;
    __syncthreads();
    long long v = ((const long long*)eidx)[threadIdx.x];
    if (v < 0 || v >= (long long)N_NODES) bad = 1;
    __syncthreads();
    if (threadIdx.x == 0) g_is64 = bad ? 0 : 1;
}

__device__ __forceinline__ int load_tgt(const void* __restrict__ eidx, int e) {
    if (g_is64) return (int)((const long long*)eidx)[N_EDGES + e];
    return ((const int*)eidx)[N_EDGES + e];
}

// ---------------- CSR build ----------------
__global__ void zero_k() {
    int i = blockIdx.x * blockDim.x + threadIdx.x;
    if (i < N_NODES) g_cnt[i] = 0;
}

__global__ void count_k(const void* __restrict__ eidx) {
    int e = blockIdx.x * blockDim.x + threadIdx.x;
    if (e < N_EDGES) atomicAdd(&g_cnt[load_tgt(eidx, e)], 1);
}

__global__ void blocksum_k() {
    int i = blockIdx.x * 1024 + threadIdx.x;
    int v = (i < N_NODES) ? g_cnt[i] : 0;
    int lane = threadIdx.x & 31, w = threadIdx.x >> 5;
    __shared__ int ws[32];
#pragma unroll
    for (int o = 16; o; o >>= 1) v += __shfl_down_sync(~0u, v, o);
    if (lane == 0) ws[w] = v;
    __syncthreads();
    if (w == 0) {
        v = ws[lane];
#pragma unroll
        for (int o = 16; o; o >>= 1) v += __shfl_down_sync(~0u, v, o);
        if (lane == 0) g_bsum[blockIdx.x] = v;
    }
}

__global__ void scanb_k() {
    __shared__ int s[64];
    int t = threadIdx.x;
    int orig = (t < NBLK) ? g_bsum[t] : 0;
    s[t] = orig;
    __syncthreads();
#pragma unroll
    for (int o = 1; o < 64; o <<= 1) {
        int v = (t >= o) ? s[t - o] : 0;
        __syncthreads();
        s[t] += v;
        __syncthreads();
    }
    if (t < NBLK) g_bsum[t] = s[t] - orig;
    if (t == 63) g_off[N_NODES] = s[63];
}

__global__ void scatter_k() {
    int tid = threadIdx.x;
    int i = blockIdx.x * 1024 + tid;
    int c = (i < N_NODES) ? g_cnt[i] : 0;
    int lane = tid & 31, w = tid >> 5;
    int inc = c;
#pragma unroll
    for (int o = 1; o < 32; o <<= 1) {
        int t = __shfl_up_sync(~0u, inc, o);
        if (lane >= o) inc += t;
    }
    __shared__ int wsum[32];
    if (lane == 31) wsum[w] = inc;
    __syncthreads();
    if (w == 0) {
        int x = wsum[lane];
#pragma unroll
        for (int o = 1; o < 32; o <<= 1) {
            int t = __shfl_up_sync(~0u, x, o);
            if (lane >= o) x += t;
        }
        wsum[lane] = x;
    }
    __syncthreads();
    int base = (w > 0) ? wsum[w - 1] : 0;
    int excl = base + inc - c;
    if (i < N_NODES) {
        int off = g_bsum[blockIdx.x] + excl;
        g_off[i] = off;
        g_cur[i] = off;
    }
}

__global__ void fill_k(const void* __restrict__ eidx) {
    int e = blockIdx.x * blockDim.x + threadIdx.x;
    if (e < N_EDGES) {
        int t = load_tgt(eidx, e);
        int p = atomicAdd(&g_cur[t], 1);
        g_elist[p] = e;
    }
}

// ---------------- mean aggregation ----------------
__global__ void agg_k(const float* __restrict__ ef) {
    int n = blockIdx.x * 8 + (threadIdx.x >> 5);
    int lane = threadIdx.x & 31;
    int base = g_off[n];
    int deg  = g_off[n + 1] - base;
    float ax = 0.f, ay = 0.f;
    const float2* ef2 = (const float2*)ef;
    int i = 0;
    for (; i + 2 <= deg; i += 2) {
        int e0 = g_elist[base + i];
        int e1 = g_elist[base + i + 1];
        float2 v0 = ef2[(size_t)e0 * 32 + lane];
        float2 v1 = ef2[(size_t)e1 * 32 + lane];
        ax += v0.x + v1.x;
        ay += v0.y + v1.y;
    }
    if (i < deg) {
        int e0 = g_elist[base + i];
        float2 v0 = ef2[(size_t)e0 * 32 + lane];
        ax += v0.x;
        ay += v0.y;
    }
    float inv = 1.f / fmaxf((float)deg, 1.f);
    float2 r;
    r.x = f2tf_f(ax * inv);
    r.y = f2tf_f(ay * inv);
    *(float2*)&g_A1[(size_t)n * K1DIM + lane * 2] = r;
}

// ---------------- node feature copy + tf32 round ----------------
__global__ void node_cvt_k(const float* __restrict__ node) {
    int idx = blockIdx.x * blockDim.x + threadIdx.x;
    if (idx < N_NODES * 64) {
        int n = idx >> 6, q = idx & 63;
        float4 v = ((const float4*)node)[idx];
        v.x = f2tf_f(v.x); v.y = f2tf_f(v.y); v.z = f2tf_f(v.z); v.w = f2tf_f(v.w);
        *(float4*)&g_A1[(size_t)n * K1DIM + EDGE_DIM + q * 4] = v;
    }
}

// ---------------- weight transpose + tf32 round: W[K][N] -> Wt[N][K] ----------------
__global__ void wt_k(const float* __restrict__ W, float* __restrict__ Wt, int K, int N) {
    __shared__ float t[32][33];
    int n0 = blockIdx.x * 32, k0 = blockIdx.y * 32;
    int tx = threadIdx.x, ty = threadIdx.y;
#pragma unroll
    for (int i = 0; i < 32; i += 8)
        t[ty + i][tx] = f2tf_f(W[(size_t)(k0 + ty + i) * N + n0 + tx]);
    __syncthreads();
#pragma unroll
    for (int i = 0; i < 32; i += 8)
        Wt[(size_t)(n0 + ty + i) * K + k0 + tx] = t[tx][ty + i];
}

// ---------------- tf32 GEMM: 128x128 tile, BK=32, 3-stage cp.async, ldmatrix ----------------
// A: [M][K] row-major (K mult of 32). Bt: [N][K] row-major. C = A @ Bt^T.
// smem per stage: A 128x32 fl (16KB, XOR-swizzled 16B chunks) + B same = 32KB; 3 stages.

__device__ __forceinline__ void mma_tf32(float& c0, float& c1, float& c2, float& c3,
                                         uint32_t a0, uint32_t a1, uint32_t a2, uint32_t a3,
                                         uint32_t b0, uint32_t b1) {
    asm volatile(
        "mma.sync.aligned.m16n8k8.row.col.f32.tf32.tf32.f32 "
        "{%0,%1,%2,%3}, {%4,%5,%6,%7}, {%8,%9}, {%0,%1,%2,%3};\n"
        : "+f"(c0), "+f"(c1), "+f"(c2), "+f"(c3)
        : "r"(a0), "r"(a1), "r"(a2), "r"(a3), "r"(b0), "r"(b1));
}

#define STAGE_BYTES 32768
#define GEMM_SMEM   (3 * STAGE_BYTES)

template <int K, int N, bool RELU, bool STORE_TF, bool GUARD>
__global__ void __launch_bounds__(256, 2) gemm_k(const float* __restrict__ A,
                                                 const float* __restrict__ Bt,
                                                 const float* __restrict__ bias,
                                                 float* __restrict__ C) {
    extern __shared__ char smem[];
    const uint32_t sb = sptr(smem);

    const int bm = blockIdx.y * 128;
    const int bn = blockIdx.x * 128;
    const int tid = threadIdx.x, lane = tid & 31, wid = tid >> 5;
    const int wm = (wid & 3) * 32, wn = (wid >> 2) * 64;
    const int g = lane >> 2, tg = lane & 3;

    // ldmatrix per-lane geometry (same row&7 mask == lane&7 for every slot)
    const int grpRow = lane & 7;
    const int grpHi  = (lane >> 3) & 1;
    const int grpK   = (lane >> 4) & 1;      // 0: k-cols 0-3, 1: k-cols 4-7 of the step
    // row-byte offsets (within a stage) for each x4 slot
    uint32_t aRB[2], bRB[4];
#pragma unroll
    for (int mi = 0; mi < 2; mi++)
        aRB[mi] = (uint32_t)(wm + 16 * mi + grpRow + 8 * grpHi) * 128;
#pragma unroll
    for (int nb = 0; nb < 4; nb++)
        bRB[nb] = 16384u + (uint32_t)(wn + 16 * nb + grpRow + 8 * grpHi) * 128;

    // cp.async loader geometry
    const int ldRow = tid >> 3;              // 0..31 (+32 per rep)
    const int ldSeg = tid & 7;

    float acc[2][8][4];
#pragma unroll
    for (int mi = 0; mi < 2; mi++)
#pragma unroll
        for (int ni = 0; ni < 8; ni++)
#pragma unroll
            for (int q = 0; q < 4; q++) acc[mi][ni][q] = 0.f;

#define LOAD_CHUNK(ci, st)                                                         \
    do {                                                                           \
        uint32_t base = sb + (uint32_t)(st) * STAGE_BYTES;                         \
        int k0 = (ci) * 32;                                                        \
        _Pragma("unroll")                                                          \
        for (int rep = 0; rep < 4; rep++) {                                        \
            int row = ldRow + rep * 32;                                            \
            uint32_t phys = (uint32_t)(ldSeg ^ (row & 7));                         \
            cpa16(base + row * 128 + phys * 16,                                    \
                  A + (size_t)(bm + row) * K + k0 + ldSeg * 4);                    \
            cpa16(base + 16384 + row * 128 + phys * 16,                            \
                  Bt + (size_t)(bn + row) * K + k0 + ldSeg * 4);                   \
        }                                                                          \
        cp_commit();                                                               \
    } while (0)

    const int NC = K / 32;
    LOAD_CHUNK(0, 0);
    LOAD_CHUNK(1, 1);

    int st = 0;            // stage of tile `it`
    for (int it = 0; it < NC; it++) {
        cp_wait<1>();
        __syncthreads();
        {
            int nt = it + 2;
            int nst = st + 2; if (nst >= 3) nst -= 3;
            if (nt < NC) LOAD_CHUNK(nt, nst);
            else cp_commit();                 // keep group accounting uniform
        }
        const uint32_t base = sb + (uint32_t)st * STAGE_BYTES;

        uint32_t af[2][2][4], bf[2][4][4];
        // prefetch k-step 0
        {
            uint32_t cb = (uint32_t)((grpK ^ grpRow) << 4);
#pragma unroll
            for (int mi = 0; mi < 2; mi++)
                ldsm4(af[0][mi][0], af[0][mi][1], af[0][mi][2], af[0][mi][3],
                      base + aRB[mi] + cb);
#pragma unroll
            for (int nb = 0; nb < 4; nb++)
                ldsm4(bf[0][nb][0], bf[0][nb][1], bf[0][nb][2], bf[0][nb][3],
                      base + bRB[nb] + cb);
        }
#pragma unroll
        for (int ks = 0; ks < 4; ks++) {
            int cur = ks & 1, nxt = cur ^ 1;
            if (ks < 3) {
                uint32_t cb = (uint32_t)(((2 * (ks + 1) + grpK) ^ grpRow) << 4);
#pragma unroll
                for (int mi = 0; mi < 2; mi++)
                    ldsm4(af[nxt][mi][0], af[nxt][mi][1], af[nxt][mi][2], af[nxt][mi][3],
                          base + aRB[mi] + cb);
#pragma unroll
                for (int nb = 0; nb < 4; nb++)
                    ldsm4(bf[nxt][nb][0], bf[nxt][nb][1], bf[nxt][nb][2], bf[nxt][nb][3],
                          base + bRB[nb] + cb);
            }
#pragma unroll
            for (int mi = 0; mi < 2; mi++)
#pragma unroll
                for (int ni = 0; ni < 8; ni++) {
                    int nb = ni >> 1, hi = ni & 1;
                    mma_tf32(acc[mi][ni][0], acc[mi][ni][1], acc[mi][ni][2], acc[mi][ni][3],
                             af[cur][mi][0], af[cur][mi][1], af[cur][mi][2], af[cur][mi][3],
                             bf[cur][nb][hi], bf[cur][nb][hi + 2]);
                }
        }
        st++; if (st >= 3) st = 0;
    }
#undef LOAD_CHUNK

    // epilogue: bias (+relu) (+tf32 round) (+row guard)
#pragma unroll
    for (int mi = 0; mi < 2; mi++) {
        int r0 = bm + wm + mi * 16 + g;
#pragma unroll
        for (int ni = 0; ni < 8; ni++) {
            int c0 = bn + wn + ni * 8 + tg * 2;
            float b0 = bias[c0];
            float b1 = bias[c0 + 1];
            float v0 = acc[mi][ni][0] + b0;
            float v1 = acc[mi][ni][1] + b1;
            float v2 = acc[mi][ni][2] + b0;
            float v3 = acc[mi][ni][3] + b1;
            if (RELU) {
                v0 = fmaxf(v0, 0.f); v1 = fmaxf(v1, 0.f);
                v2 = fmaxf(v2, 0.f); v3 = fmaxf(v3, 0.f);
            }
            if (STORE_TF) {
                v0 = f2tf_f(v0); v1 = f2tf_f(v1);
                v2 = f2tf_f(v2); v3 = f2tf_f(v3);
            }
            if (!GUARD || r0 < N_NODES) {
                C[(size_t)r0 * N + c0] = v0;
                C[(size_t)r0 * N + c0 + 1] = v1;
            }
            if (!GUARD || r0 + 8 < N_NODES) {
                C[(size_t)(r0 + 8) * N + c0] = v2;
                C[(size_t)(r0 + 8) * N + c0 + 1] = v3;
            }
        }
    }
}

// ---------------- launch ----------------
extern "C" void kernel_launch(void* const* d_in, const int* in_sizes, int n_in,
                              void* d_out, int out_size) {
    const float* node = (const float*)d_in[0];
    const void*  eidx = d_in[1];
    const float* ef   = (const float*)d_in[2];
    const float* W1   = (const float*)d_in[3];
    const float* b1   = (const float*)d_in[4];
    const float* W2   = (const float*)d_in[5];
    const float* b2   = (const float*)d_in[6];
    float* out = (float*)d_out;

    cudaFuncSetAttribute(gemm_k<K1DIM, HIDDEN, true, true, false>,
                         cudaFuncAttributeMaxDynamicSharedMemorySize, GEMM_SMEM);
    cudaFuncSetAttribute(gemm_k<HIDDEN, OUT_DIM, false, false, true>,
                         cudaFuncAttributeMaxDynamicSharedMemorySize, GEMM_SMEM);

    float* g_h_ptr;    cudaGetSymbolAddress((void**)&g_h_ptr, g_h);
    float* g_A1_ptr;   cudaGetSymbolAddress((void**)&g_A1_ptr, g_A1);
    float* g_W1t_ptr;  cudaGetSymbolAddress((void**)&g_W1t_ptr, g_W1t);
    float* g_W2t_ptr;  cudaGetSymbolAddress((void**)&g_W2t_ptr, g_W2t);

    detect_k<<<1, 1024>>>(eidx);
    zero_k<<<(N_NODES + 255) / 256, 256>>>();
    count_k<<<(N_EDGES + 255) / 256, 256>>>(eidx);
    blocksum_k<<<NBLK, 1024>>>();
    scanb_k<<<1, 64>>>();
    scatter_k<<<NBLK, 1024>>>();
    fill_k<<<(N_EDGES + 255) / 256, 256>>>(eidx);
    agg_k<<<N_NODES / 8, 256>>>(ef);
    node_cvt_k<<<(N_NODES * 64 + 255) / 256, 256>>>(node);
    wt_k<<<dim3(HIDDEN / 32, K1DIM / 32), dim3(32, 8)>>>(W1, g_W1t_ptr, K1DIM, HIDDEN);
    wt_k<<<dim3(OUT_DIM / 32, HIDDEN / 32), dim3(32, 8)>>>(W2, g_W2t_ptr, HIDDEN, OUT_DIM);

    gemm_k<K1DIM, HIDDEN, true, true, false>
        <<<dim3(HIDDEN / 128, M_PAD / 128), 256, GEMM_SMEM>>>(g_A1_ptr, g_W1t_ptr, b1, g_h_ptr);
    gemm_k<HIDDEN, OUT_DIM, false, false, true>
        <<<dim3(OUT_DIM / 128, M_PAD / 128), 256, GEMM_SMEM>>>(g_h_ptr, g_W2t_ptr, b2, out);
}

// round 6
// speedup vs baseline: 2.0967x; 1.0917x over previous
#include <cuda_runtime.h>
#include <cuda_fp16.h>
#include <cstdint>

#define N_NODES 50000
#define N_EDGES 800000
#define EDGE_DIM 64
#define NODE_DIM 256
#define HIDDEN   512
#define OUT_DIM  256
#define K1DIM    (EDGE_DIM + NODE_DIM)   // 320
#define M_PAD    50048                   // 391 * 128
#define NBLK     49

// ---------------- device scratch ----------------
__device__ int    g_cnt[N_NODES];
__device__ int    g_off[N_NODES + 1];
__device__ int    g_cur[N_NODES];
__device__ int    g_bsum[NBLK];
__device__ int    g_elist[N_EDGES];
__device__ __half g_A1[(size_t)M_PAD * K1DIM];      // fp16 [agg | node]
__device__ __half g_h[(size_t)M_PAD * HIDDEN];      // fp16 hidden
__device__ __half g_W1t[HIDDEN * K1DIM];            // W1^T [N][K] fp16
__device__ __half g_W2t[OUT_DIM * HIDDEN];          // W2^T [N][K] fp16
__device__ int    g_is64;

// ---------------- helpers ----------------
__device__ __forceinline__ uint32_t sptr(const void* p) {
    return (uint32_t)__cvta_generic_to_shared(p);
}
__device__ __forceinline__ void cpa16(uint32_t d, const void* s) {
    asm volatile("cp.async.cg.shared.global [%0], [%1], 16;" :: "r"(d), "l"(s));
}
__device__ __forceinline__ void cp_commit() { asm volatile("cp.async.commit_group;"); }
template <int W> __device__ __forceinline__ void cp_wait() {
    asm volatile("cp.async.wait_group %0;" :: "n"(W));
}
__device__ __forceinline__ void ldsm4(uint32_t& r0, uint32_t& r1, uint32_t& r2,
                                      uint32_t& r3, uint32_t addr) {
    asm volatile("ldmatrix.sync.aligned.m8n8.x4.shared.b16 {%0,%1,%2,%3}, [%4];"
                 : "=r"(r0), "=r"(r1), "=r"(r2), "=r"(r3) : "r"(addr));
}
__device__ __forceinline__ void mma_f16(float& c0, float& c1, float& c2, float& c3,
                                        uint32_t a0, uint32_t a1, uint32_t a2, uint32_t a3,
                                        uint32_t b0, uint32_t b1) {
    asm volatile(
        "mma.sync.aligned.m16n8k16.row.col.f32.f16.f16.f32 "
        "{%0,%1,%2,%3}, {%4,%5,%6,%7}, {%8,%9}, {%0,%1,%2,%3};\n"
        : "+f"(c0), "+f"(c1), "+f"(c2), "+f"(c3)
        : "r"(a0), "r"(a1), "r"(a2), "r"(a3), "r"(b0), "r"(b1));
}

// ---------------- dtype detection ----------------
__global__ void detect_k(const void* __restrict__ eidx) {
    __shared__ int bad;
    if (threadIdx.x == 0) bad = 0;
    __syncthreads();
    long long v = ((const long long*)eidx)[threadIdx.x];
    if (v < 0 || v >= (long long)N_NODES) bad = 1;
    __syncthreads();
    if (threadIdx.x == 0) g_is64 = bad ? 0 : 1;
}

__device__ __forceinline__ int load_tgt(const void* __restrict__ eidx, int e) {
    if (g_is64) return (int)((const long long*)eidx)[N_EDGES + e];
    return ((const int*)eidx)[N_EDGES + e];
}

// ---------------- CSR build ----------------
__global__ void zero_k() {
    int i = blockIdx.x * blockDim.x + threadIdx.x;
    if (i < N_NODES) g_cnt[i] = 0;
}

__global__ void count_k(const void* __restrict__ eidx) {
    int e = blockIdx.x * blockDim.x + threadIdx.x;
    if (e < N_EDGES) atomicAdd(&g_cnt[load_tgt(eidx, e)], 1);
}

__global__ void blocksum_k() {
    int i = blockIdx.x * 1024 + threadIdx.x;
    int v = (i < N_NODES) ? g_cnt[i] : 0;
    int lane = threadIdx.x & 31, w = threadIdx.x >> 5;
    __shared__ int ws[32];
#pragma unroll
    for (int o = 16; o; o >>= 1) v += __shfl_down_sync(~0u, v, o);
    if (lane == 0) ws[w] = v;
    __syncthreads();
    if (w == 0) {
        v = ws[lane];
#pragma unroll
        for (int o = 16; o; o >>= 1) v += __shfl_down_sync(~0u, v, o);
        if (lane == 0) g_bsum[blockIdx.x] = v;
    }
}

__global__ void scanb_k() {
    __shared__ int s[64];
    int t = threadIdx.x;
    int orig = (t < NBLK) ? g_bsum[t] : 0;
    s[t] = orig;
    __syncthreads();
#pragma unroll
    for (int o = 1; o < 64; o <<= 1) {
        int v = (t >= o) ? s[t - o] : 0;
        __syncthreads();
        s[t] += v;
        __syncthreads();
    }
    if (t < NBLK) g_bsum[t] = s[t] - orig;
    if (t == 63) g_off[N_NODES] = s[63];
}

__global__ void scatter_k() {
    int tid = threadIdx.x;
    int i = blockIdx.x * 1024 + tid;
    int c = (i < N_NODES) ? g_cnt[i] : 0;
    int lane = tid & 31, w = tid >> 5;
    int inc = c;
#pragma unroll
    for (int o = 1; o < 32; o <<= 1) {
        int t = __shfl_up_sync(~0u, inc, o);
        if (lane >= o) inc += t;
    }
    __shared__ int wsum[32];
    if (lane == 31) wsum[w] = inc;
    __syncthreads();
    if (w == 0) {
        int x = wsum[lane];
#pragma unroll
        for (int o = 1; o < 32; o <<= 1) {
            int t = __shfl_up_sync(~0u, x, o);
            if (lane >= o) x += t;
        }
        wsum[lane] = x;
    }
    __syncthreads();
    int base = (w > 0) ? wsum[w - 1] : 0;
    int excl = base + inc - c;
    if (i < N_NODES) {
        int off = g_bsum[blockIdx.x] + excl;
        g_off[i] = off;
        g_cur[i] = off;
    }
}

__global__ void fill_k(const void* __restrict__ eidx) {
    int e = blockIdx.x * blockDim.x + threadIdx.x;
    if (e < N_EDGES) {
        int t = load_tgt(eidx, e);
        int p = atomicAdd(&g_cur[t], 1);
        g_elist[p] = e;
    }
}

// ---------------- mean aggregation: one warp per node -> fp16 into g_A1 ----------------
__global__ void agg_k(const float* __restrict__ ef) {
    int n = blockIdx.x * 8 + (threadIdx.x >> 5);
    int lane = threadIdx.x & 31;
    int base = g_off[n];
    int deg  = g_off[n + 1] - base;
    float ax = 0.f, ay = 0.f;
    const float2* ef2 = (const float2*)ef;
    int i = 0;
    for (; i + 2 <= deg; i += 2) {
        int e0 = g_elist[base + i];
        int e1 = g_elist[base + i + 1];
        float2 v0 = ef2[(size_t)e0 * 32 + lane];
        float2 v1 = ef2[(size_t)e1 * 32 + lane];
        ax += v0.x + v1.x;
        ay += v0.y + v1.y;
    }
    if (i < deg) {
        int e0 = g_elist[base + i];
        float2 v0 = ef2[(size_t)e0 * 32 + lane];
        ax += v0.x;
        ay += v0.y;
    }
    float inv = 1.f / fmaxf((float)deg, 1.f);
    *(__half2*)&g_A1[(size_t)n * K1DIM + lane * 2] = __floats2half2_rn(ax * inv, ay * inv);
}

// ---------------- node feature copy -> fp16 into g_A1 cols [64,320) ----------------
__global__ void node_cvt_k(const float* __restrict__ node) {
    int idx = blockIdx.x * blockDim.x + threadIdx.x;   // over N_NODES*64 float4s
    if (idx < N_NODES * 64) {
        int n = idx >> 6, q = idx & 63;
        float4 v = ((const float4*)node)[idx];
        __half2 h0 = __floats2half2_rn(v.x, v.y);
        __half2 h1 = __floats2half2_rn(v.z, v.w);
        __half2* dst = (__half2*)&g_A1[(size_t)n * K1DIM + EDGE_DIM + q * 4];
        dst[0] = h0;
        dst[1] = h1;
    }
}

// ---------------- weight transpose -> fp16: W[K][N] -> Wt[N][K] ----------------
__global__ void wt_k(const float* __restrict__ W, __half* __restrict__ Wt, int K, int N) {
    __shared__ float t[32][33];
    int n0 = blockIdx.x * 32, k0 = blockIdx.y * 32;
    int tx = threadIdx.x, ty = threadIdx.y;
#pragma unroll
    for (int i = 0; i < 32; i += 8)
        t[ty + i][tx] = W[(size_t)(k0 + ty + i) * N + n0 + tx];
    __syncthreads();
#pragma unroll
    for (int i = 0; i < 32; i += 8)
        Wt[(size_t)(n0 + ty + i) * K + k0 + tx] = __float2half_rn(t[tx][ty + i]);
}

// ---------------- fp16 GEMM: 128x128 tile, BK=64, 3-stage cp.async, ldmatrix ----------------
// A: [M][K] fp16 row-major (K mult of 64). Bt: [N][K] fp16 row-major. C = A @ Bt^T.
// Stage: A 128 rows x 128B (16KB) + B same = 32KB. Rows XOR-swizzled in 16B chunks.

#define STAGE_BYTES 32768
#define GEMM_SMEM   (3 * STAGE_BYTES)

template <int K, int N, bool RELU, bool HALF_OUT, bool GUARD>
__global__ void __launch_bounds__(256, 2) gemm_k(const __half* __restrict__ A,
                                                 const __half* __restrict__ Bt,
                                                 const float* __restrict__ bias,
                                                 void* __restrict__ Cv) {
    extern __shared__ char smem[];
    const uint32_t sb = sptr(smem);

    const int bm = blockIdx.y * 128;
    const int bn = blockIdx.x * 128;
    const int tid = threadIdx.x, lane = tid & 31, wid = tid >> 5;
    const int wm = (wid & 3) * 32, wn = (wid >> 2) * 64;
    const int g = lane >> 2, tg = lane & 3;

    // ldmatrix lane geometry (PTX fragment layouts for m16n8k16 f16):
    // A x4: lanes 0-7 -> (m 0-7, kLo), 8-15 -> (m+8, kLo), 16-23 -> (m 0-7, kHi), 24-31 -> (m+8, kHi)
    // B x4: lanes 0-7 -> (n 0-7, kLo), 8-15 -> (n 0-7, kHi), 16-23 -> (n+8, kLo), 24-31 -> (n+8, kHi)
    const int l7 = lane & 7;
    const int aRowSel   = (lane >> 3) & 1;
    const int aChunkSel = (lane >> 4) & 1;
    const int bRowSel   = (lane >> 4) & 1;
    const int bChunkSel = (lane >> 3) & 1;

    uint32_t aRB[2], bRB[4];
    int aR7[2], bR7[4];
#pragma unroll
    for (int mi = 0; mi < 2; mi++) {
        int row = wm + 16 * mi + l7 + 8 * aRowSel;
        aRB[mi] = (uint32_t)row * 128;
        aR7[mi] = row & 7;
    }
#pragma unroll
    for (int nb = 0; nb < 4; nb++) {
        int row = wn + 16 * nb + l7 + 8 * bRowSel;
        bRB[nb] = 16384u + (uint32_t)row * 128;
        bR7[nb] = row & 7;
    }

    const int ldRow = tid >> 3;              // 0..31 (+32 per rep)
    const int ldSeg = tid & 7;               // 16B segment within 128B row

    float acc[2][8][4];
#pragma unroll
    for (int mi = 0; mi < 2; mi++)
#pragma unroll
        for (int ni = 0; ni < 8; ni++)
#pragma unroll
            for (int q = 0; q < 4; q++) acc[mi][ni][q] = 0.f;

#define LOAD_CHUNK(ci, st)                                                         \
    do {                                                                           \
        uint32_t base = sb + (uint32_t)(st) * STAGE_BYTES;                         \
        int k0 = (ci) * 64;                                                        \
        _Pragma("unroll")                                                          \
        for (int rep = 0; rep < 4; rep++) {                                        \
            int row = ldRow + rep * 32;                                            \
            uint32_t phys = (uint32_t)(ldSeg ^ (row & 7));                         \
            cpa16(base + row * 128 + phys * 16,                                    \
                  A + (size_t)(bm + row) * K + k0 + ldSeg * 8);                    \
            cpa16(base + 16384 + row * 128 + phys * 16,                            \
                  Bt + (size_t)(bn + row) * K + k0 + ldSeg * 8);                   \
        }                                                                          \
        cp_commit();                                                               \
    } while (0)

    const int NC = K / 64;
    LOAD_CHUNK(0, 0);
    LOAD_CHUNK(1, 1);

    int st = 0;
    for (int it = 0; it < NC; it++) {
        cp_wait<1>();
        __syncthreads();
        {
            int nt = it + 2;
            int nst = st + 2; if (nst >= 3) nst -= 3;
            if (nt < NC) LOAD_CHUNK(nt, nst);
            else cp_commit();
        }
        const uint32_t base = sb + (uint32_t)st * STAGE_BYTES;

#pragma unroll
        for (int ks = 0; ks < 4; ks++) {          // 4 k-steps of k=16 (2 chunks each)
            uint32_t af[2][4], bf[4][4];
#pragma unroll
            for (int mi = 0; mi < 2; mi++) {
                uint32_t cb = (uint32_t)(((2 * ks + aChunkSel) ^ aR7[mi]) << 4);
                ldsm4(af[mi][0], af[mi][1], af[mi][2], af[mi][3], base + aRB[mi] + cb);
            }
#pragma unroll
            for (int nb = 0; nb < 4; nb++) {
                uint32_t cb = (uint32_t)(((2 * ks + bChunkSel) ^ bR7[nb]) << 4);
                ldsm4(bf[nb][0], bf[nb][1], bf[nb][2], bf[nb][3], base + bRB[nb] + cb);
            }
#pragma unroll
            for (int mi = 0; mi < 2; mi++)
#pragma unroll
                for (int ni = 0; ni < 8; ni++) {
                    int nb = ni >> 1, p = ni & 1;
                    mma_f16(acc[mi][ni][0], acc[mi][ni][1], acc[mi][ni][2], acc[mi][ni][3],
                            af[mi][0], af[mi][1], af[mi][2], af[mi][3],
                            bf[nb][2 * p], bf[nb][2 * p + 1]);
                }
        }
        st++; if (st >= 3) st = 0;
    }
#undef LOAD_CHUNK

    // epilogue: bias (+relu); store fp16 (h) or fp32 (out, guarded)
#pragma unroll
    for (int mi = 0; mi < 2; mi++) {
        int r0 = bm + wm + mi * 16 + g;
#pragma unroll
        for (int ni = 0; ni < 8; ni++) {
            int c0 = bn + wn + ni * 8 + tg * 2;
            float b0 = bias[c0];
            float b1 = bias[c0 + 1];
            float v0 = acc[mi][ni][0] + b0;
            float v1 = acc[mi][ni][1] + b1;
            float v2 = acc[mi][ni][2] + b0;
            float v3 = acc[mi][ni][3] + b1;
            if (RELU) {
                v0 = fmaxf(v0, 0.f); v1 = fmaxf(v1, 0.f);
                v2 = fmaxf(v2, 0.f); v3 = fmaxf(v3, 0.f);
            }
            if (HALF_OUT) {
                __half* Ch = (__half*)Cv;
                *(__half2*)&Ch[(size_t)r0 * N + c0] = __floats2half2_rn(v0, v1);
                *(__half2*)&Ch[(size_t)(r0 + 8) * N + c0] = __floats2half2_rn(v2, v3);
            } else {
                float* Cf = (float*)Cv;
                if (!GUARD || r0 < N_NODES) {
                    Cf[(size_t)r0 * N + c0] = v0;
                    Cf[(size_t)r0 * N + c0 + 1] = v1;
                }
                if (!GUARD || r0 + 8 < N_NODES) {
                    Cf[(size_t)(r0 + 8) * N + c0] = v2;
                    Cf[(size_t)(r0 + 8) * N + c0 + 1] = v3;
                }
            }
        }
    }
}

// ---------------- launch ----------------
extern "C" void kernel_launch(void* const* d_in, const int* in_sizes, int n_in,
                              void* d_out, int out_size) {
    const float* node = (const float*)d_in[0];
    const void*  eidx = d_in[1];
    const float* ef   = (const float*)d_in[2];
    const float* W1   = (const float*)d_in[3];
    const float* b1   = (const float*)d_in[4];
    const float* W2   = (const float*)d_in[5];
    const float* b2   = (const float*)d_in[6];

    cudaFuncSetAttribute(gemm_k<K1DIM, HIDDEN, true, true, false>,
                         cudaFuncAttributeMaxDynamicSharedMemorySize, GEMM_SMEM);
    cudaFuncSetAttribute(gemm_k<HIDDEN, OUT_DIM, false, false, true>,
                         cudaFuncAttributeMaxDynamicSharedMemorySize, GEMM_SMEM);

    __half* g_h_ptr;    cudaGetSymbolAddress((void**)&g_h_ptr, g_h);
    __half* g_A1_ptr;   cudaGetSymbolAddress((void**)&g_A1_ptr, g_A1);
    __half* g_W1t_ptr;  cudaGetSymbolAddress((void**)&g_W1t_ptr, g_W1t);
    __half* g_W2t_ptr;  cudaGetSymbolAddress((void**)&g_W2t_ptr, g_W2t);

    detect_k<<<1, 1024>>>(eidx);
    zero_k<<<(N_NODES + 255) / 256, 256>>>();
    count_k<<<(N_EDGES + 255) / 256, 256>>>(eidx);
    blocksum_k<<<NBLK, 1024>>>();
    scanb_k<<<1, 64>>>();
    scatter_k<<<NBLK, 1024>>>();
    fill_k<<<(N_EDGES + 255) / 256, 256>>>(eidx);
    agg_k<<<N_NODES / 8, 256>>>(ef);
    node_cvt_k<<<(N_NODES * 64 + 255) / 256, 256>>>(node);
    wt_k<<<dim3(HIDDEN / 32, K1DIM / 32), dim3(32, 8)>>>(W1, g_W1t_ptr, K1DIM, HIDDEN);
    wt_k<<<dim3(OUT_DIM / 32, HIDDEN / 32), dim3(32, 8)>>>(W2, g_W2t_ptr, HIDDEN, OUT_DIM);

    gemm_k<K1DIM, HIDDEN, true, true, false>
        <<<dim3(HIDDEN / 128, M_PAD / 128), 256, GEMM_SMEM>>>(g_A1_ptr, g_W1t_ptr, b1, (void*)g_h_ptr);
    gemm_k<HIDDEN, OUT_DIM, false, false, true>
        <<<dim3(OUT_DIM / 128, M_PAD / 128), 256, GEMM_SMEM>>>(g_h_ptr, g_W2t_ptr, b2, d_out);
}

// round 9
// speedup vs baseline: 2.8102x; 1.3402x over previous
#include <cuda_runtime.h>
#include <cuda_fp16.h>
#include <cstdint>

#define N_NODES 50000
#define N_EDGES 800000
#define EDGE_DIM 64
#define NODE_DIM 256
#define HIDDEN   512
#define OUT_DIM  256
#define K1DIM    (EDGE_DIM + NODE_DIM)   // 320
#define M_PAD    50048                   // 391 * 128
#define NBLK     49

// ---------------- device scratch ----------------
__device__ int    g_cnt[N_NODES];
__device__ int    g_off[N_NODES + 1];
__device__ int    g_cur[N_NODES];
__device__ int    g_aggv[NBLK];
__device__ int    g_incl[NBLK];
__device__ int    g_flags[NBLK];
__device__ int    g_elist[N_EDGES];
__device__ __half g_A1[(size_t)M_PAD * K1DIM];      // fp16 [agg | node]
__device__ __half g_h[(size_t)M_PAD * HIDDEN];      // fp16 hidden
__device__ __half g_W1t[HIDDEN * K1DIM];            // W1^T [N][K] fp16
__device__ __half g_W2t[OUT_DIM * HIDDEN];          // W2^T [N][K] fp16
__device__ int    g_is64;

// ---------------- helpers ----------------
__device__ __forceinline__ uint32_t sptr(const void* p) {
    return (uint32_t)__cvta_generic_to_shared(p);
}
__device__ __forceinline__ void cpa16(uint32_t d, const void* s) {
    asm volatile("cp.async.cg.shared.global [%0], [%1], 16;" :: "r"(d), "l"(s));
}
__device__ __forceinline__ void cp_commit() { asm volatile("cp.async.commit_group;"); }
template <int W> __device__ __forceinline__ void cp_wait() {
    asm volatile("cp.async.wait_group %0;" :: "n"(W));
}
__device__ __forceinline__ void ldsm4(uint32_t& r0, uint32_t& r1, uint32_t& r2,
                                      uint32_t& r3, uint32_t addr) {
    asm volatile("ldmatrix.sync.aligned.m8n8.x4.shared.b16 {%0,%1,%2,%3}, [%4];"
                 : "=r"(r0), "=r"(r1), "=r"(r2), "=r"(r3) : "r"(addr));
}
__device__ __forceinline__ void mma_f16(float& c0, float& c1, float& c2, float& c3,
                                        uint32_t a0, uint32_t a1, uint32_t a2, uint32_t a3,
                                        uint32_t b0, uint32_t b1) {
    asm volatile(
        "mma.sync.aligned.m16n8k16.row.col.f32.f16.f16.f32 "
        "{%0,%1,%2,%3}, {%4,%5,%6,%7}, {%8,%9}, {%0,%1,%2,%3};\n"
        : "+f"(c0), "+f"(c1), "+f"(c2), "+f"(c3)
        : "r"(a0), "r"(a1), "r"(a2), "r"(a3), "r"(b0), "r"(b1));
}

// ---------------- dtype detection ----------------
__global__ void detect_k(const void* __restrict__ eidx) {
    __shared__ int bad;
    if (threadIdx.x == 0) bad = 0;
    __syncthreads();
    long long v = ((const long long*)eidx)[threadIdx.x];
    if (v < 0 || v >= (long long)N_NODES) bad = 1;
    __syncthreads();
    if (threadIdx.x == 0) g_is64 = bad ? 0 : 1;
}

__device__ __forceinline__ int load_tgt(const void* __restrict__ eidx, int e) {
    if (g_is64) return (int)((const long long*)eidx)[N_EDGES + e];
    return ((const int*)eidx)[N_EDGES + e];
}

// ---------------- CSR build ----------------
__global__ void zero_k() {
    int i = blockIdx.x * blockDim.x + threadIdx.x;
    if (i < N_NODES) g_cnt[i] = 0;
    if (i < NBLK) g_flags[i] = 0;
}

__global__ void count_k(const void* __restrict__ eidx) {
    int e = blockIdx.x * blockDim.x + threadIdx.x;
    if (e < N_EDGES) atomicAdd(&g_cnt[load_tgt(eidx, e)], 1);
}

// single-kernel decoupled-lookback exclusive scan of g_cnt -> g_off/g_cur
__global__ void scan_k() {
    __shared__ int shw[32];
    __shared__ int sh_excl;
    const int bid = blockIdx.x, tid = threadIdx.x;
    const int i = bid * 1024 + tid;
    const int c = (i < N_NODES) ? g_cnt[i] : 0;
    const int lane = tid & 31, w = tid >> 5;

    int inc = c;
#pragma unroll
    for (int o = 1; o < 32; o <<= 1) {
        int t = __shfl_up_sync(~0u, inc, o);
        if (lane >= o) inc += t;
    }
    if (lane == 31) shw[w] = inc;
    __syncthreads();
    if (w == 0) {
        int x = shw[lane];
#pragma unroll
        for (int o = 1; o < 32; o <<= 1) {
            int t = __shfl_up_sync(~0u, x, o);
            if (lane >= o) x += t;
        }
        shw[lane] = x;
    }
    __syncthreads();
    const int base = w ? shw[w - 1] : 0;
    const int local_excl = base + inc - c;
    const int total = shw[31];

    if (tid == 0) {
        if (bid == 0) {
            g_incl[0] = total;
            __threadfence();
            atomicExch(&g_flags[0], 2);
            sh_excl = 0;
        } else {
            g_aggv[bid] = total;
            __threadfence();
            atomicExch(&g_flags[bid], 1);
            int excl = 0, p = bid - 1;
            while (true) {
                int f;
                do { f = atomicAdd(&g_flags[p], 0); } while (f == 0);
                if (f == 2) { excl += atomicAdd(&g_incl[p], 0); break; }
                excl += atomicAdd(&g_aggv[p], 0);
                p--;
            }
            sh_excl = excl;
            g_incl[bid] = excl + total;
            __threadfence();
            atomicExch(&g_flags[bid], 2);
        }
    }
    __syncthreads();
    const int excl = sh_excl;
    if (i < N_NODES) {
        g_off[i] = excl + local_excl;
        g_cur[i] = excl + local_excl;
    }
    if (bid == NBLK - 1 && tid == 1023) g_off[N_NODES] = excl + total;
}

__global__ void fill_k(const void* __restrict__ eidx) {
    int e = blockIdx.x * blockDim.x + threadIdx.x;
    if (e < N_EDGES) {
        int t = load_tgt(eidx, e);
        int p = atomicAdd(&g_cur[t], 1);
        g_elist[p] = e;
    }
}

// ---------------- mean aggregation: one warp per node -> fp16 into g_A1 ----------------
__global__ void agg_k(const float* __restrict__ ef) {
    int n = blockIdx.x * 8 + (threadIdx.x >> 5);
    int lane = threadIdx.x & 31;
    int base = g_off[n];
    int deg  = g_off[n + 1] - base;
    float ax = 0.f, ay = 0.f;
    const float2* ef2 = (const float2*)ef;
    int i = 0;
    for (; i + 2 <= deg; i += 2) {
        int e0 = g_elist[base + i];
        int e1 = g_elist[base + i + 1];
        float2 v0 = ef2[(size_t)e0 * 32 + lane];
        float2 v1 = ef2[(size_t)e1 * 32 + lane];
        ax += v0.x + v1.x;
        ay += v0.y + v1.y;
    }
    if (i < deg) {
        int e0 = g_elist[base + i];
        float2 v0 = ef2[(size_t)e0 * 32 + lane];
        ax += v0.x;
        ay += v0.y;
    }
    float inv = 1.f / fmaxf((float)deg, 1.f);
    *(__half2*)&g_A1[(size_t)n * K1DIM + lane * 2] = __floats2half2_rn(ax * inv, ay * inv);
}

// ---------------- node feature copy -> fp16 into g_A1 cols [64,320) ----------------
__global__ void node_cvt_k(const float* __restrict__ node) {
    int idx = blockIdx.x * blockDim.x + threadIdx.x;
    if (idx < N_NODES * 64) {
        int n = idx >> 6, q = idx & 63;
        float4 v = ((const float4*)node)[idx];
        __half2 h0 = __floats2half2_rn(v.x, v.y);
        __half2 h1 = __floats2half2_rn(v.z, v.w);
        __half2* dst = (__half2*)&g_A1[(size_t)n * K1DIM + EDGE_DIM + q * 4];
        dst[0] = h0;
        dst[1] = h1;
    }
}

// ---------------- weight transpose -> fp16: both weights in one launch ----------------
// z=0: W1 [K1DIM][HIDDEN] -> g_W1t [HIDDEN][K1DIM]   grid (16,10)
// z=1: W2 [HIDDEN][OUT_DIM] -> g_W2t [OUT_DIM][HIDDEN] grid (8,16)
__global__ void wt_k(const float* __restrict__ W1, const float* __restrict__ W2) {
    const int z = blockIdx.z;
    const int K = z ? HIDDEN : K1DIM;
    const int N = z ? OUT_DIM : HIDDEN;
    if (blockIdx.x * 32 >= N || blockIdx.y * 32 >= K) return;
    const float* W = z ? W2 : W1;
    __half* Wt = z ? g_W2t : g_W1t;
    __shared__ float t[32][33];
    int n0 = blockIdx.x * 32, k0 = blockIdx.y * 32;
    int tx = threadIdx.x, ty = threadIdx.y;
#pragma unroll
    for (int i = 0; i < 32; i += 8)
        t[ty + i][tx] = W[(size_t)(k0 + ty + i) * N + n0 + tx];
    __syncthreads();
#pragma unroll
    for (int i = 0; i < 32; i += 8)
        Wt[(size_t)(n0 + ty + i) * K + k0 + tx] = __float2half_rn(t[tx][ty + i]);
}

// ---------------- fp16 GEMM: 128x128 tile, BK=64, 3-stage cp.async, ldmatrix ----------------
#define STAGE_BYTES 32768
#define GEMM_SMEM   (3 * STAGE_BYTES)

template <int K, int N, bool RELU, bool HALF_OUT, bool GUARD>
__global__ void __launch_bounds__(256, 2) gemm_k(const __half* __restrict__ A,
                                                 const __half* __restrict__ Bt,
                                                 const float* __restrict__ bias,
                                                 void* __restrict__ Cv) {
    extern __shared__ char smem[];
    const uint32_t sb = sptr(smem);

    const int bm = blockIdx.y * 128;
    const int bn = blockIdx.x * 128;
    const int tid = threadIdx.x, lane = tid & 31, wid = tid >> 5;
    const int wm = (wid & 3) * 32, wn = (wid >> 2) * 64;
    const int g = lane >> 2, tg = lane & 3;

    const int l7 = lane & 7;
    const int aRowSel   = (lane >> 3) & 1;
    const int aChunkSel = (lane >> 4) & 1;
    const int bRowSel   = (lane >> 4) & 1;
    const int bChunkSel = (lane >> 3) & 1;

    uint32_t aRB[2], bRB[4];
    int aR7[2], bR7[4];
#pragma unroll
    for (int mi = 0; mi < 2; mi++) {
        int row = wm + 16 * mi + l7 + 8 * aRowSel;
        aRB[mi] = (uint32_t)row * 128;
        aR7[mi] = row & 7;
    }
#pragma unroll
    for (int nb = 0; nb < 4; nb++) {
        int row = wn + 16 * nb + l7 + 8 * bRowSel;
        bRB[nb] = 16384u + (uint32_t)row * 128;
        bR7[nb] = row & 7;
    }

    const int ldRow = tid >> 3;
    const int ldSeg = tid & 7;

    float acc[2][8][4];
#pragma unroll
    for (int mi = 0; mi < 2; mi++)
#pragma unroll
        for (int ni = 0; ni < 8; ni++)
#pragma unroll
            for (int q = 0; q < 4; q++) acc[mi][ni][q] = 0.f;

#define LOAD_CHUNK(ci, st)                                                         \
    do {                                                                           \
        uint32_t base = sb + (uint32_t)(st) * STAGE_BYTES;                         \
        int k0 = (ci) * 64;                                                        \
        _Pragma("unroll")                                                          \
        for (int rep = 0; rep < 4; rep++) {                                        \
            int row = ldRow + rep * 32;                                            \
            uint32_t phys = (uint32_t)(ldSeg ^ (row & 7));                         \
            cpa16(base + row * 128 + phys * 16,                                    \
                  A + (size_t)(bm + row) * K + k0 + ldSeg * 8);                    \
            cpa16(base + 16384 + row * 128 + phys * 16,                            \
                  Bt + (size_t)(bn + row) * K + k0 + ldSeg * 8);                   \
        }                                                                          \
        cp_commit();                                                               \
    } while (0)

    const int NC = K / 64;
    LOAD_CHUNK(0, 0);
    LOAD_CHUNK(1, 1);

    int st = 0;
    for (int it = 0; it < NC; it++) {
        cp_wait<1>();
        __syncthreads();
        {
            int nt = it + 2;
            int nst = st + 2; if (nst >= 3) nst -= 3;
            if (nt < NC) LOAD_CHUNK(nt, nst);
            else cp_commit();
        }
        const uint32_t base = sb + (uint32_t)st * STAGE_BYTES;

#pragma unroll
        for (int ks = 0; ks < 4; ks++) {
            uint32_t af[2][4], bf[4][4];
#pragma unroll
            for (int mi = 0; mi < 2; mi++) {
                uint32_t cb = (uint32_t)(((2 * ks + aChunkSel) ^ aR7[mi]) << 4);
                ldsm4(af[mi][0], af[mi][1], af[mi][2], af[mi][3], base + aRB[mi] + cb);
            }
#pragma unroll
            for (int nb = 0; nb < 4; nb++) {
                uint32_t cb = (uint32_t)(((2 * ks + bChunkSel) ^ bR7[nb]) << 4);
                ldsm4(bf[nb][0], bf[nb][1], bf[nb][2], bf[nb][3], base + bRB[nb] + cb);
            }
#pragma unroll
            for (int mi = 0; mi < 2; mi++)
#pragma unroll
                for (int ni = 0; ni < 8; ni++) {
                    int nb = ni >> 1, p = ni & 1;
                    mma_f16(acc[mi][ni][0], acc[mi][ni][1], acc[mi][ni][2], acc[mi][ni][3],
                            af[mi][0], af[mi][1], af[mi][2], af[mi][3],
                            bf[nb][2 * p], bf[nb][2 * p + 1]);
                }
        }
        st++; if (st >= 3) st = 0;
    }
#undef LOAD_CHUNK

#pragma unroll
    for (int mi = 0; mi < 2; mi++) {
        int r0 = bm + wm + mi * 16 + g;
#pragma unroll
        for (int ni = 0; ni < 8; ni++) {
            int c0 = bn + wn + ni * 8 + tg * 2;
            float b0 = bias[c0];
            float b1 = bias[c0 + 1];
            float v0 = acc[mi][ni][0] + b0;
            float v1 = acc[mi][ni][1] + b1;
            float v2 = acc[mi][ni][2] + b0;
            float v3 = acc[mi][ni][3] + b1;
            if (RELU) {
                v0 = fmaxf(v0, 0.f); v1 = fmaxf(v1, 0.f);
                v2 = fmaxf(v2, 0.f); v3 = fmaxf(v3, 0.f);
            }
            if (HALF_OUT) {
                __half* Ch = (__half*)Cv;
                *(__half2*)&Ch[(size_t)r0 * N + c0] = __floats2half2_rn(v0, v1);
                *(__half2*)&Ch[(size_t)(r0 + 8) * N + c0] = __floats2half2_rn(v2, v3);
            } else {
                float* Cf = (float*)Cv;
                if (!GUARD || r0 < N_NODES) {
                    Cf[(size_t)r0 * N + c0] = v0;
                    Cf[(size_t)r0 * N + c0 + 1] = v1;
                }
                if (!GUARD || r0 + 8 < N_NODES) {
                    Cf[(size_t)(r0 + 8) * N + c0] = v2;
                    Cf[(size_t)(r0 + 8) * N + c0 + 1] = v3;
                }
            }
        }
    }
}

// ---------------- launch ----------------
extern "C" void kernel_launch(void* const* d_in, const int* in_sizes, int n_in,
                              void* d_out, int out_size) {
    const float* node = (const float*)d_in[0];
    const void*  eidx = d_in[1];
    const float* ef   = (const float*)d_in[2];
    const float* W1   = (const float*)d_in[3];
    const float* b1   = (const float*)d_in[4];
    const float* W2   = (const float*)d_in[5];
    const float* b2   = (const float*)d_in[6];

    cudaFuncSetAttribute(gemm_k<K1DIM, HIDDEN, true, true, false>,
                         cudaFuncAttributeMaxDynamicSharedMemorySize, GEMM_SMEM);
    cudaFuncSetAttribute(gemm_k<HIDDEN, OUT_DIM, false, false, true>,
                         cudaFuncAttributeMaxDynamicSharedMemorySize, GEMM_SMEM);

    __half* g_h_ptr;    cudaGetSymbolAddress((void**)&g_h_ptr, g_h);
    __half* g_A1_ptr;   cudaGetSymbolAddress((void**)&g_A1_ptr, g_A1);
    __half* g_W1t_ptr;  cudaGetSymbolAddress((void**)&g_W1t_ptr, g_W1t);
    __half* g_W2t_ptr;  cudaGetSymbolAddress((void**)&g_W2t_ptr, g_W2t);

    detect_k<<<1, 1024>>>(eidx);                            // 1
    zero_k<<<(N_NODES + 255) / 256, 256>>>();               // 2
    count_k<<<(N_EDGES + 255) / 256, 256>>>(eidx);          // 3
    scan_k<<<NBLK, 1024>>>();                               // 4
    fill_k<<<(N_EDGES + 255) / 256, 256>>>(eidx);           // 5
    agg_k<<<N_NODES / 8, 256>>>(ef);                        // 6 <- profiled by ncu (-s 5 -c 1)
    node_cvt_k<<<(N_NODES * 64 + 255) / 256, 256>>>(node);  // 7
    wt_k<<<dim3(16, 16, 2), dim3(32, 8)>>>(W1, W2);         // 8

    gemm_k<K1DIM, HIDDEN, true, true, false>
        <<<dim3(HIDDEN / 128, M_PAD / 128), 256, GEMM_SMEM>>>(g_A1_ptr, g_W1t_ptr, b1, (void*)g_h_ptr);
    gemm_k<HIDDEN, OUT_DIM, false, false, true>
        <<<dim3(OUT_DIM / 128, M_PAD / 128), 256, GEMM_SMEM>>>(g_h_ptr, g_W2t_ptr, b2, d_out);
}